// round 7
// baseline (speedup 1.0000x reference)
#include <cuda_runtime.h>
#include <cuda_bf16.h>
#include <math.h>

#define B_SZ 4
#define T_LEN 1024
#define D_MODEL 128
#define D_STATE 64
#define ED 256
#define DT_RANK 8
#define ROWS (B_SZ * T_LEN)          // 4096
#define EPS 1e-5f
#define LOG2E 1.44269504088896340736f

// ---------------- scratch (device globals; no allocation allowed) -------------
__device__ float g_z[ROWS * D_MODEL];        // z residual
__device__ float g_zn[ROWS * D_MODEL];       // rmsnorm(z)
__device__ float g_xz[ROWS * 2 * ED];        // in_proj output (xs_raw | zg)
__device__ float g_xs[ROWS * ED];            // conv+silu output
__device__ float g_dbc[ROWS * 136];          // x_proj output (dt|B|C)
__device__ float g_delta_t[B_SZ * ED * T_LEN]; // delta, (b,e,t) layout
__device__ float g_dxs_t[B_SZ * ED * T_LEN];   // delta*xs, (b,e,t) layout
__device__ float g_y[ROWS * ED];             // scan output y
__device__ float g_yg[ROWS * ED];            // gated y
__device__ float g_core[ROWS * D_MODEL];     // out_proj output

// ---------------- kernel 1: z = z_seq + aux@auxW^T + aux_b ; zn = rmsnorm(z) --
__global__ void pre_kernel(const float* __restrict__ z_seq,
                           const float* __restrict__ aux_t,
                           const float* __restrict__ aux_W,
                           const float* __restrict__ aux_b,
                           const float* __restrict__ rms_w) {
    int row = blockIdx.x;                // b*T + t
    int d = threadIdx.x;                 // 0..127
    float a0 = aux_t[row * 3 + 0];
    float a1 = aux_t[row * 3 + 1];
    float a2 = aux_t[row * 3 + 2];
    float z = z_seq[row * D_MODEL + d]
            + a0 * aux_W[d * 3 + 0] + a1 * aux_W[d * 3 + 1] + a2 * aux_W[d * 3 + 2]
            + aux_b[d];
    float s = z * z;
    #pragma unroll
    for (int o = 16; o; o >>= 1) s += __shfl_xor_sync(0xffffffffu, s, o);
    __shared__ float ws[4];
    if ((d & 31) == 0) ws[d >> 5] = s;
    __syncthreads();
    float ms = (ws[0] + ws[1] + ws[2] + ws[3]) * (1.0f / 128.0f);
    float zn = z * rsqrtf(ms + EPS) * rms_w[d];
    g_z[row * D_MODEL + d] = z;
    g_zn[row * D_MODEL + d] = zn;
}

// ---------------- generic NT GEMM: C[m][n] = sum_k A[m][k] * B[n][k] ----------
// BM=64, BN=64, BK=32, 256 threads, 4x4 microtile. M % 64 == 0, K % 32 == 0.
__global__ __launch_bounds__(256) void gemm_nt_kernel(
    const float* __restrict__ A, const float* __restrict__ B,
    float* __restrict__ C, int M, int N, int K) {
    __shared__ float As[32][68];
    __shared__ float Bs[32][68];
    const int tid = threadIdx.x;
    const int tcol = tid & 15;           // 16 col groups
    const int trow = tid >> 4;           // 16 row groups
    const int m0 = blockIdx.y * 64;
    const int n0 = blockIdx.x * 64;
    float acc[4][4] = {};
    for (int k0 = 0; k0 < K; k0 += 32) {
        // load A tile 64x32 -> As[k][m]
        #pragma unroll
        for (int idx = tid; idx < 64 * 8; idx += 256) {
            int r = idx >> 3;            // m row 0..63
            int c4 = idx & 7;            // k group
            float4 v = *(const float4*)&A[(size_t)(m0 + r) * K + k0 + c4 * 4];
            As[c4 * 4 + 0][r] = v.x; As[c4 * 4 + 1][r] = v.y;
            As[c4 * 4 + 2][r] = v.z; As[c4 * 4 + 3][r] = v.w;
        }
        // load B tile 64x32 -> Bs[k][n] (zero-fill rows beyond N)
        #pragma unroll
        for (int idx = tid; idx < 64 * 8; idx += 256) {
            int r = idx >> 3;
            int c4 = idx & 7;
            float4 v = make_float4(0.f, 0.f, 0.f, 0.f);
            if (n0 + r < N)
                v = *(const float4*)&B[(size_t)(n0 + r) * K + k0 + c4 * 4];
            Bs[c4 * 4 + 0][r] = v.x; Bs[c4 * 4 + 1][r] = v.y;
            Bs[c4 * 4 + 2][r] = v.z; Bs[c4 * 4 + 3][r] = v.w;
        }
        __syncthreads();
        #pragma unroll
        for (int k = 0; k < 32; ++k) {
            float4 ra = *(const float4*)&As[k][trow * 4];
            float4 rb = *(const float4*)&Bs[k][tcol * 4];
            float a_[4] = {ra.x, ra.y, ra.z, ra.w};
            float b_[4] = {rb.x, rb.y, rb.z, rb.w};
            #pragma unroll
            for (int i = 0; i < 4; ++i)
                #pragma unroll
                for (int j = 0; j < 4; ++j)
                    acc[i][j] = fmaf(a_[i], b_[j], acc[i][j]);
        }
        __syncthreads();
    }
    #pragma unroll
    for (int i = 0; i < 4; ++i) {
        int m = m0 + trow * 4 + i;
        #pragma unroll
        for (int j = 0; j < 4; ++j) {
            int n = n0 + tcol * 4 + j;
            if (n < N) C[(size_t)m * N + n] = acc[i][j];
        }
    }
}

// ---------------- kernel 3: depthwise causal conv(4) + bias + silu ------------
__global__ void conv_kernel(const float* __restrict__ conv_W,
                            const float* __restrict__ conv_b) {
    int idx = blockIdx.x * blockDim.x + threadIdx.x;   // over ROWS*ED
    if (idx >= ROWS * ED) return;
    int e = idx & (ED - 1);
    int bt = idx >> 8;
    int t = bt & (T_LEN - 1);
    int b = bt >> 10;
    float acc = conv_b[e];
    #pragma unroll
    for (int k = 0; k < 4; ++k) {
        int tt = t - 3 + k;
        if (tt >= 0)
            acc = fmaf(g_xz[(size_t)(b * T_LEN + tt) * (2 * ED) + e], conv_W[e * 4 + k], acc);
    }
    float s = acc / (1.0f + expf(-acc));   // silu
    g_xs[idx] = s;
}

// ---------------- kernel 5: delta = softplus(dt @ dtW^T + dt_b); dxs ----------
// CTA: (t-tile of 64, b). 256 threads = 64 t x 4 e-strides.
__global__ __launch_bounds__(256) void delta_kernel(
    const float* __restrict__ dt_W, const float* __restrict__ dt_b) {
    int b = blockIdx.y;
    int t0 = blockIdx.x * 64;
    __shared__ float sdt[64][9];
    __shared__ float sW[ED * 8];
    __shared__ float sb[ED];
    int tid = threadIdx.x;
    if (tid < 128) {
        int r = tid >> 1, h = tid & 1;
        float4 v = *(const float4*)&g_dbc[(size_t)(b * T_LEN + t0 + r) * 136 + h * 4];
        sdt[r][h * 4 + 0] = v.x; sdt[r][h * 4 + 1] = v.y;
        sdt[r][h * 4 + 2] = v.z; sdt[r][h * 4 + 3] = v.w;
    }
    for (int i = tid; i < ED * 8; i += 256) sW[i] = dt_W[i];
    if (tid < ED) sb[tid] = dt_b[tid];
    __syncthreads();
    int tx = tid & 63;
    int ey = tid >> 6;
    for (int e = ey; e < ED; e += 4) {
        float acc = sb[e];
        #pragma unroll
        for (int r = 0; r < 8; ++r) acc = fmaf(sdt[tx][r], sW[e * 8 + r], acc);
        float dl = (acc > 20.0f) ? acc : log1pf(expf(acc));
        size_t o = ((size_t)b * ED + e) * T_LEN + t0 + tx;
        g_delta_t[o] = dl;
        g_dxs_t[o] = dl * g_xs[(size_t)(b * T_LEN + t0 + tx) * ED + e];
    }
}

// ---------------- kernel 6: selective scan ------------------------------------
// CTA: (e-tile of 8, b). 8 warps; warp w owns e = e0+w; lane owns n = {2l, 2l+1}.
#define CT 64
__global__ __launch_bounds__(256) void scan_kernel(const float* __restrict__ A_log) {
    __shared__ float sB[CT][64];
    __shared__ float sC[CT][64];
    __shared__ float sD[8][CT];
    __shared__ float sDX[8][CT];
    __shared__ float sY[8][CT];
    int b = blockIdx.y;
    int e0 = blockIdx.x * 8;
    int tid = threadIdx.x;
    int w = tid >> 5, lane = tid & 31;
    int e = e0 + w;
    float k0 = -expf(A_log[e * D_STATE + 2 * lane])     * LOG2E;
    float k1 = -expf(A_log[e * D_STATE + 2 * lane + 1]) * LOG2E;
    float h0 = 0.f, h1 = 0.f;
    const float* dT  = g_delta_t + ((size_t)b * ED + e) * T_LEN;
    const float* dxT = g_dxs_t   + ((size_t)b * ED + e) * T_LEN;
    for (int t0 = 0; t0 < T_LEN; t0 += CT) {
        // stage B/C tiles (shared by all 8 e's)
        #pragma unroll
        for (int idx = tid; idx < CT * 16; idx += 256) {
            int r = idx >> 4, c4 = idx & 15;
            const float* row = &g_dbc[(size_t)(b * T_LEN + t0 + r) * 136];
            float4 vb = *(const float4*)(row + DT_RANK + c4 * 4);
            float4 vc = *(const float4*)(row + DT_RANK + D_STATE + c4 * 4);
            *(float4*)&sB[r][c4 * 4] = vb;
            *(float4*)&sC[r][c4 * 4] = vc;
        }
        // per-warp delta / delta*xs (coalesced from (b,e,t) layout)
        sD[w][lane]       = dT[t0 + lane];
        sD[w][lane + 32]  = dT[t0 + lane + 32];
        sDX[w][lane]      = dxT[t0 + lane];
        sDX[w][lane + 32] = dxT[t0 + lane + 32];
        __syncthreads();
        #pragma unroll 4
        for (int t = 0; t < CT; ++t) {
            float d  = sD[w][t];
            float dx = sDX[w][t];
            float a0 = exp2f(d * k0);
            float a1 = exp2f(d * k1);
            float2 Bv = *(const float2*)&sB[t][2 * lane];
            float2 Cv = *(const float2*)&sC[t][2 * lane];
            h0 = fmaf(a0, h0, dx * Bv.x);
            h1 = fmaf(a1, h1, dx * Bv.y);
            float p = h0 * Cv.x + h1 * Cv.y;
            #pragma unroll
            for (int o = 16; o; o >>= 1) p += __shfl_xor_sync(0xffffffffu, p, o);
            if (lane == 0) sY[w][t] = p;
        }
        __syncthreads();
        // write y tile (b,t,e) layout
        #pragma unroll
        for (int idx = tid; idx < 8 * CT; idx += 256) {
            int j = idx & 7, tt = idx >> 3;
            g_y[(size_t)(b * T_LEN + t0 + tt) * ED + e0 + j] = sY[j][tt];
        }
        // next load phase overwrites sB/sC/sD/sDX (not read here); sY rewrite is
        // fenced by the post-load __syncthreads of the next iteration.
    }
}

// ---------------- kernel 7: gate: yg = (y + D*xs) * silu(zg) -------------------
__global__ void gate_kernel(const float* __restrict__ D_param) {
    int idx = blockIdx.x * blockDim.x + threadIdx.x;
    if (idx >= ROWS * ED) return;
    int e = idx & (ED - 1);
    size_t bt = (size_t)(idx >> 8);
    float zg = g_xz[bt * (2 * ED) + ED + e];
    float s = zg / (1.0f + expf(-zg));
    g_yg[idx] = (g_y[idx] + D_param[e] * g_xs[idx]) * s;
}

// ---------------- kernel 9: r = core + 2z; LayerNorm ---------------------------
__global__ void ln_kernel(const float* __restrict__ ln_w,
                          const float* __restrict__ ln_b,
                          float* __restrict__ out) {
    int row = blockIdx.x;
    int d = threadIdx.x;
    float r = g_core[row * D_MODEL + d] + 2.0f * g_z[row * D_MODEL + d];
    float s = r;
    #pragma unroll
    for (int o = 16; o; o >>= 1) s += __shfl_xor_sync(0xffffffffu, s, o);
    __shared__ float a4[4], b4[4];
    if ((d & 31) == 0) a4[d >> 5] = s;
    __syncthreads();
    float mu = (a4[0] + a4[1] + a4[2] + a4[3]) * (1.0f / 128.0f);
    float c = r - mu;
    float q = c * c;
    #pragma unroll
    for (int o = 16; o; o >>= 1) q += __shfl_xor_sync(0xffffffffu, q, o);
    if ((d & 31) == 0) b4[d >> 5] = q;
    __syncthreads();
    float var = (b4[0] + b4[1] + b4[2] + b4[3]) * (1.0f / 128.0f);
    out[row * D_MODEL + d] = c * rsqrtf(var + EPS) * ln_w[d] + ln_b[d];
}

// ---------------- launch --------------------------------------------------------
extern "C" void kernel_launch(void* const* d_in, const int* in_sizes, int n_in,
                              void* d_out, int out_size) {
    const float* z_seq      = (const float*)d_in[0];
    const float* aux_tensor = (const float*)d_in[1];
    const float* aux_W      = (const float*)d_in[2];
    const float* aux_b      = (const float*)d_in[3];
    const float* ln_w       = (const float*)d_in[4];
    const float* ln_b       = (const float*)d_in[5];
    const float* rms_w      = (const float*)d_in[6];
    const float* in_proj_W  = (const float*)d_in[7];
    const float* conv_W     = (const float*)d_in[8];
    const float* conv_b     = (const float*)d_in[9];
    const float* x_proj_W   = (const float*)d_in[10];
    const float* dt_W       = (const float*)d_in[11];
    const float* dt_b       = (const float*)d_in[12];
    const float* A_log      = (const float*)d_in[13];
    const float* D_param    = (const float*)d_in[14];
    const float* out_proj_W = (const float*)d_in[15];
    float* out = (float*)d_out;

    float *p_z, *p_zn, *p_xz, *p_xs, *p_dbc, *p_yg, *p_core;
    cudaGetSymbolAddress((void**)&p_z,    g_z);
    cudaGetSymbolAddress((void**)&p_zn,   g_zn);
    cudaGetSymbolAddress((void**)&p_xz,   g_xz);
    cudaGetSymbolAddress((void**)&p_xs,   g_xs);
    cudaGetSymbolAddress((void**)&p_dbc,  g_dbc);
    cudaGetSymbolAddress((void**)&p_yg,   g_yg);
    cudaGetSymbolAddress((void**)&p_core, g_core);

    // 1. pre: z + rmsnorm
    pre_kernel<<<ROWS, 128>>>(z_seq, aux_tensor, aux_W, aux_b, rms_w);

    // 2. in_proj: xz = zn @ in_proj_W^T   (4096 x 512, K=128)
    gemm_nt_kernel<<<dim3(512 / 64, ROWS / 64), 256>>>(p_zn, in_proj_W, p_xz,
                                                       ROWS, 2 * ED, D_MODEL);

    // 3. depthwise conv + silu
    conv_kernel<<<(ROWS * ED) / 256, 256>>>(conv_W, conv_b);

    // 4. x_proj: dbc = xs @ x_proj_W^T    (4096 x 136, K=256)
    gemm_nt_kernel<<<dim3(3, ROWS / 64), 256>>>(p_xs, x_proj_W, p_dbc,
                                                ROWS, 136, ED);

    // 5. delta + dxs (transposed (b,e,t) layout for the scan)
    delta_kernel<<<dim3(T_LEN / 64, B_SZ), 256>>>(dt_W, dt_b);

    // 6. selective scan
    scan_kernel<<<dim3(ED / 8, B_SZ), 256>>>(A_log);

    // 7. gate
    gate_kernel<<<(ROWS * ED) / 256, 256>>>(D_param);

    // 8. out_proj: core = yg @ out_proj_W^T   (4096 x 128, K=256)
    gemm_nt_kernel<<<dim3(2, ROWS / 64), 256>>>(p_yg, out_proj_W, p_core,
                                                ROWS, D_MODEL, ED);

    // 9. residual (core + 2z) + LayerNorm
    ln_kernel<<<ROWS, 128>>>(ln_w, ln_b, out);
}